// round 7
// baseline (speedup 1.0000x reference)
#include <cuda_runtime.h>

#define N_NODES 20000
#define N_EDGES 200000
#define D 32
#define R 100
#define EPS 1e-5f
#define NB 400          // histogram/scatter blocks
#define EPB 500         // edges per block (NB*EPB == N_EDGES)
#define FULL 0xffffffffu

// ---------------- device scratch (static, no runtime allocation) --------
__device__ int   g_dcnt[N_NODES];           // per-dst edge counts (self-zeroing)
__device__ int   g_doff[N_NODES + 1];       // CSR offsets by dst
__device__ int   g_dcur[N_NODES];           // scatter cursors by dst
__device__ int   g_bh[R * NB];              // per-(relation, block) histogram
__device__ int   g_boff[R * NB];            // per-(relation, block) base offset
__device__ int   g_hist[R];                 // per-relation totals
__device__ int   g_off[R + 1];              // exclusive scan of g_hist
__device__ int   g_chunkbase[R + 1];        // exclusive scan of chunk counts
__device__ int   g_ssrc[N_EDGES];           // src sorted by etype
__device__ int   g_dpos[N_EDGES];           // dst-order slot per etype-sorted edge
__device__ float g_msg[N_EDGES * D];        // messages, stored in DST order
__device__ float g_sum[D], g_sumsq[D];
__device__ int   g_nchunk;

// ---------------- K1: per-block etype histograms + global dst histogram --
__global__ void __launch_bounds__(256) k1_hist(const int* __restrict__ etype,
                                               const int* __restrict__ dst) {
    __shared__ int sh[R];
    for (int i = threadIdx.x; i < R; i += blockDim.x) sh[i] = 0;
    __syncthreads();
    int base = blockIdx.x * EPB;
    for (int i = threadIdx.x; i < EPB; i += blockDim.x) {
        atomicAdd(&sh[etype[base + i]], 1);
        atomicAdd(&g_dcnt[dst[base + i]], 1);   // 20K spread addrs: cheap
    }
    __syncthreads();
    for (int r = threadIdx.x; r < R; r += blockDim.x)
        g_bh[r * NB + blockIdx.x] = sh[r];
}

// ---------------- K2: ALL scans, register-batched, one 1024-thread block --
// Also re-zeros g_dcnt (for the next graph replay) and g_sum/g_sumsq.
__global__ void __launch_bounds__(1024) k2_scan() {
    __shared__ int wsum[32], wbase[32];
    const int lane = threadIdx.x & 31;
    const int wid  = threadIdx.x >> 5;
    const int tid  = threadIdx.x;

    if (tid < D) { g_sum[tid] = 0.f; g_sumsq[tid] = 0.f; }

    // ===== phase A: dst-count exclusive scan (register-batched) =====
    {
        const int NPT = 20;                       // 1024*20 >= 20000
        int base_i = tid * NPT;
        int v[NPT];
        int lsum = 0;
#pragma unroll
        for (int j = 0; j < NPT; j++) {
            int i = base_i + j;
            v[j] = (i < N_NODES) ? g_dcnt[i] : 0; // batched loads, MLP=20
            lsum += v[j];
        }
#pragma unroll
        for (int j = 0; j < NPT; j++) {           // self-zero for next replay
            int i = base_i + j;
            if (i < N_NODES) g_dcnt[i] = 0;
        }
        int s = lsum;
#pragma unroll
        for (int d = 1; d < 32; d <<= 1) {
            int t = __shfl_up_sync(FULL, s, d);
            if (lane >= d) s += t;
        }
        int excl = s - lsum;
        if (lane == 31) wsum[wid] = s;
        __syncthreads();
        if (wid == 0) {
            int v2 = wsum[lane], s2 = v2;
#pragma unroll
            for (int d = 1; d < 32; d <<= 1) {
                int t = __shfl_up_sync(FULL, s2, d);
                if (lane >= d) s2 += t;
            }
            wbase[lane] = s2 - v2;
            if (lane == 31) g_doff[N_NODES] = s2;
        }
        __syncthreads();
        int run = wbase[wid] + excl;
#pragma unroll
        for (int j = 0; j < NPT; j++) {
            int i = base_i + j;
            if (i < N_NODES) { g_doff[i] = run; g_dcur[i] = run; run += v[j]; }
        }
    }
    __syncthreads();

    // ===== phase B: per-relation local scans over blocks (warp/relation) ==
    for (int r = wid; r < R; r += 32) {
        const int CPL = (NB + 31) / 32;           // 13
        int v[CPL], pre[CPL], tot[CPL];
#pragma unroll
        for (int j = 0; j < CPL; j++) {
            int b = j * 32 + lane;
            v[j] = (b < NB) ? g_bh[r * NB + b] : 0;
        }
#pragma unroll
        for (int j = 0; j < CPL; j++) {           // independent scans (ILP)
            int s = v[j];
#pragma unroll
            for (int d = 1; d < 32; d <<= 1) {
                int t = __shfl_up_sync(FULL, s, d);
                if (lane >= d) s += t;
            }
            pre[j] = s - v[j];
            tot[j] = __shfl_sync(FULL, s, 31);
        }
        int base = 0;
#pragma unroll
        for (int j = 0; j < CPL; j++) {
            int b = j * 32 + lane;
            if (b < NB) g_boff[r * NB + b] = base + pre[j];  // local offsets
            base += tot[j];
        }
        if (lane == 0) g_hist[r] = base;
    }
    __syncthreads();

    // ===== phase C: scan relation totals + chunk counts (warp 0) =====
    if (wid == 0) {
        int acc = 0, cacc = 0;
        for (int b0 = 0; b0 < R; b0 += 32) {
            int r = b0 + lane;
            int hv = (r < R) ? g_hist[r] : 0;
            int cv = (hv + 31) >> 5;
            int hs = hv, cs = cv;
#pragma unroll
            for (int d = 1; d < 32; d <<= 1) {
                int t1 = __shfl_up_sync(FULL, hs, d);
                int t2 = __shfl_up_sync(FULL, cs, d);
                if (lane >= d) { hs += t1; cs += t2; }
            }
            if (r < R) {
                g_off[r] = acc + hs - hv;
                g_chunkbase[r] = cacc + cs - cv;
            }
            acc  += __shfl_sync(FULL, hs, 31);
            cacc += __shfl_sync(FULL, cs, 31);
        }
        if (lane == 0) { g_off[R] = acc; g_chunkbase[R] = cacc; g_nchunk = cacc; }
    }
    __syncthreads();

    // ===== phase D: add relation bases to boff (fully parallel) =====
    for (int idx = tid; idx < R * NB; idx += 1024)
        g_boff[idx] += g_off[idx / NB];
}

// ---------------- K3: dual scatter (etype perm + dst slot) ----------------
__global__ void __launch_bounds__(256) k3_scatter(
    const int* __restrict__ etype, const int* __restrict__ src,
    const int* __restrict__ dst)
{
    __shared__ int cur[R];
    for (int r = threadIdx.x; r < R; r += blockDim.x)
        cur[r] = g_boff[r * NB + blockIdx.x];
    __syncthreads();
    int base = blockIdx.x * EPB;
    for (int i = threadIdx.x; i < EPB; i += blockDim.x) {
        int e = base + i;
        int pos = atomicAdd(&cur[etype[e]], 1);    // shared, low contention
        g_ssrc[pos] = src[e];
        g_dpos[pos] = atomicAdd(&g_dcur[dst[e]], 1);  // 20K spread addrs
    }
}

// ---------------- K4: GEMV pass — one-wave grid, W reuse, 2-edge ILP ------
// Warp owns a CONTIGUOUS chunk range; consecutive chunks usually share the
// relation, so the 32-LDG weight load is skipped. Inner loop processes two
// edges at once: 16 LDS.128 + 64 FMA over 8 independent chains.
__global__ void __launch_bounds__(128, 7) k4_compute(
    const float* __restrict__ h, const float* __restrict__ weight)
{
    __shared__ __align__(16) float tile[4][32][32];
    __shared__ int s_cb[R + 1], s_off[R + 1];
    const int lane = threadIdx.x & 31;
    const int wid  = threadIdx.x >> 5;
    const int warp = (blockIdx.x * blockDim.x + threadIdx.x) >> 5;
    const int nwarp = (gridDim.x * blockDim.x) >> 5;

    for (int i = threadIdx.x; i <= R; i += blockDim.x) {
        s_cb[i] = g_chunkbase[i];
        s_off[i] = g_off[i];
    }
    __syncthreads();
    const int nchunk = g_nchunk;

    float lsum = 0.f, lsq = 0.f;

    int c0 = (int)((long long)warp * nchunk / nwarp);
    int c1 = (int)((long long)(warp + 1) * nchunk / nwarp);

    if (c0 < c1) {
        // relation of first chunk (binary search), then advance incrementally
        int lo2 = 0, hi2 = R;
        while (lo2 < hi2) {
            int mid = (lo2 + hi2 + 1) >> 1;
            if (s_cb[mid] <= c0) lo2 = mid; else hi2 = mid - 1;
        }
        int r = lo2;
        bool needW = true;
        float wc[32];

        for (int c = c0; c < c1; c++) {
            while (s_cb[r + 1] <= c) { r++; needW = true; }
            if (needW) {
                const float* wp = weight + r * (D * D) + lane;
#pragma unroll
                for (int k = 0; k < 32; k++) wc[k] = wp[k * 32];
                needW = false;
            }
            int s = s_off[r] + ((c - s_cb[r]) << 5);
            int n = min(32, s_off[r + 1] - s);

            int sj = 0, dj = 0;
            if (lane < n) { sj = g_ssrc[s + lane]; dj = g_dpos[s + lane]; }
            for (int j = 0; j < n; j++) {
                int sje = __shfl_sync(FULL, sj, j);
                tile[wid][j][lane] = h[sje * D + lane];   // coalesced 128B
            }
            __syncwarp();

            int j = 0;
            for (; j + 2 <= n; j += 2) {
                const float4* rowA = (const float4*)tile[wid][j];
                const float4* rowB = (const float4*)tile[wid][j + 1];
                float a0 = 0.f, a1 = 0.f, a2 = 0.f, a3 = 0.f;
                float b0 = 0.f, b1 = 0.f, b2 = 0.f, b3 = 0.f;
#pragma unroll
                for (int kk = 0; kk < 8; kk++) {
                    float4 qa = rowA[kk];                 // LDS.128 broadcast
                    float4 qb = rowB[kk];
                    a0 = fmaf(qa.x, wc[4 * kk + 0], a0);
                    b0 = fmaf(qb.x, wc[4 * kk + 0], b0);
                    a1 = fmaf(qa.y, wc[4 * kk + 1], a1);
                    b1 = fmaf(qb.y, wc[4 * kk + 1], b1);
                    a2 = fmaf(qa.z, wc[4 * kk + 2], a2);
                    b2 = fmaf(qb.z, wc[4 * kk + 2], b2);
                    a3 = fmaf(qa.w, wc[4 * kk + 3], a3);
                    b3 = fmaf(qb.w, wc[4 * kk + 3], b3);
                }
                float accA = fmaxf((a0 + a1) + (a2 + a3), 0.f);
                float accB = fmaxf((b0 + b1) + (b2 + b3), 0.f);
                lsum += accA + accB;
                lsq = fmaf(accA, accA, lsq);
                lsq = fmaf(accB, accB, lsq);
                g_msg[__shfl_sync(FULL, dj, j) * D + lane] = accA;
                g_msg[__shfl_sync(FULL, dj, j + 1) * D + lane] = accB;
            }
            if (j < n) {
                const float4* row = (const float4*)tile[wid][j];
                float a0 = 0.f, a1 = 0.f, a2 = 0.f, a3 = 0.f;
#pragma unroll
                for (int kk = 0; kk < 8; kk++) {
                    float4 hq = row[kk];
                    a0 = fmaf(hq.x, wc[4 * kk + 0], a0);
                    a1 = fmaf(hq.y, wc[4 * kk + 1], a1);
                    a2 = fmaf(hq.z, wc[4 * kk + 2], a2);
                    a3 = fmaf(hq.w, wc[4 * kk + 3], a3);
                }
                float acc = fmaxf((a0 + a1) + (a2 + a3), 0.f);
                lsum += acc;
                lsq = fmaf(acc, acc, lsq);
                g_msg[__shfl_sync(FULL, dj, j) * D + lane] = acc;
            }
            __syncwarp();
        }
    }

    __shared__ float ssum[4][32], ssq[4][32];
    ssum[wid][lane] = lsum; ssq[wid][lane] = lsq;
    __syncthreads();
    if (wid == 0) {
        float ts = ssum[0][lane] + ssum[1][lane] + ssum[2][lane] + ssum[3][lane];
        float tq = ssq[0][lane] + ssq[1][lane] + ssq[2][lane] + ssq[3][lane];
        atomicAdd(&g_sum[lane], ts);
        atomicAdd(&g_sumsq[lane], tq);
    }
}

// ---------------- K6: contiguous per-node reduce + folded BN affine ------
__global__ void __launch_bounds__(128) k6_reduce(
    float* __restrict__ out, const float* __restrict__ gamma,
    const float* __restrict__ beta)
{
    __shared__ float s_sc[32], s_sh[32];
    if (threadIdx.x < 32) {
        int d = threadIdx.x;
        float inv_e = 1.0f / (float)N_EDGES;
        float mu = g_sum[d] * inv_e;
        float var = fmaxf(g_sumsq[d] * inv_e - mu * mu, 0.f);
        float scale = rsqrtf(var + EPS) * gamma[d];
        s_sc[d] = scale;
        s_sh[d] = beta[d] - mu * scale;
    }
    __syncthreads();

    const int lane = threadIdx.x & 31;
    const int node = (blockIdx.x * blockDim.x + threadIdx.x) >> 5;
    if (node >= N_NODES) return;

    int off = g_doff[node], end = g_doff[node + 1];
    int cnt = end - off;
    float acc = 0.f;
    const float* p = g_msg + (size_t)off * D + lane;
    int i = 0;
#pragma unroll 4
    for (; i + 4 <= cnt; i += 4) {                 // contiguous rows, MLP=4
        float v0 = p[(i + 0) * D];
        float v1 = p[(i + 1) * D];
        float v2 = p[(i + 2) * D];
        float v3 = p[(i + 3) * D];
        acc += (v0 + v1) + (v2 + v3);
    }
    for (; i < cnt; i++) acc += p[i * D];

    float v = 0.f;
    if (cnt > 0) v = fmaf(acc * (1.0f / (float)cnt), s_sc[lane], s_sh[lane]);
    out[node * D + lane] = v;
}

extern "C" void kernel_launch(void* const* d_in, const int* in_sizes, int n_in,
                              void* d_out, int out_size) {
    const float* h      = (const float*)d_in[0];
    const float* weight = (const float*)d_in[1];
    const float* gamma  = (const float*)d_in[2];
    const float* beta   = (const float*)d_in[3];
    const int*   src    = (const int*)d_in[4];
    const int*   dst    = (const int*)d_in[5];
    const int*   etype  = (const int*)d_in[6];
    float* out = (float*)d_out;

    k1_hist<<<NB, 256>>>(etype, dst);
    k2_scan<<<1, 1024>>>();
    k3_scatter<<<NB, 256>>>(etype, src, dst);
    k4_compute<<<1036, 128>>>(h, weight);    // 148 SMs x 7 blocks = one wave
    k6_reduce<<<(N_NODES + 3) / 4, 128>>>(out, gamma, beta);
}

// round 8
// speedup vs baseline: 1.0131x; 1.0131x over previous
#include <cuda_runtime.h>

#define N_NODES 20000
#define N_EDGES 200000
#define D 32
#define R 100
#define EPS 1e-5f
#define NB 400          // KA blocks
#define EPB 500         // edges per KA block
#define KB_BLOCKS 1036  // 148 SMs x 7 blocks: exactly one wave
#define FULL 0xffffffffu

// ---------------- device scratch (static, no runtime allocation) --------
__device__ int   g_dcnt[N_NODES];           // per-dst counts (self-zeroing)
__device__ int   g_doff[N_NODES + 1];       // CSR offsets by dst
__device__ int   g_dcur[N_NODES];           // scatter cursors by dst
__device__ int   g_bh[R * NB];              // per-(relation, block) histogram
__device__ int   g_boff[R * NB];            // per-(rel, block) local offsets
__device__ int   g_off[R + 1];              // relation bases
__device__ int   g_chunkbase[R + 1];        // chunk-count scan
__device__ int   g_ssrc[N_EDGES];           // src sorted by etype
__device__ int   g_dpos[N_EDGES];           // dst-order slot per sorted edge
__device__ float g_msg[N_EDGES * D];        // messages in DST order
__device__ float g_sum[D], g_sumsq[D];
__device__ int   g_nchunk;
// grid barriers (generation-monotonic; state valid across graph replays)
__device__ int g_genA, g_cntA, g_genB, g_cntB;

__device__ __forceinline__ void grid_barrier(int* cnt, volatile int* gen, int nb) {
    __threadfence();                 // release this thread's prior writes
    __syncthreads();                 // all block threads' writes fenced/visible
    if (threadIdx.x == 0) {
        int t = *gen;                // all blocks read same generation
        if (atomicAdd(cnt, 1) == nb - 1) {
            *(volatile int*)cnt = 0;
            __threadfence();
            *gen = t + 1;            // release
        } else {
            while (*gen < t + 1) __nanosleep(64);
        }
        __threadfence();             // acquire
    }
    __syncthreads();
}

// ======================= KA: hist + scans + scatter ======================
__global__ void __launch_bounds__(256) ka_sort(
    const int* __restrict__ etype, const int* __restrict__ src,
    const int* __restrict__ dst)
{
    __shared__ int sh[R];            // hist, then cursors
    const int t = threadIdx.x;
    const int blk = blockIdx.x;
    const int lane = t & 31;
    const int wid = t >> 5;

    // ---- phase 1: histograms (keep edge data in registers) ----
    for (int i = t; i < R; i += 256) sh[i] = 0;
    if (blk == 2 && t < D) { g_sum[t] = 0.f; g_sumsq[t] = 0.f; }
    __syncthreads();
    const int base = blk * EPB;
    int e0 = base + t, e1 = base + t + 256;
    bool p1 = (t + 256 < EPB);
    int et0 = etype[e0], d0 = dst[e0], s0 = src[e0];
    int et1 = 0, d1 = 0, s1 = 0;
    if (p1) { et1 = etype[e1]; d1 = dst[e1]; s1 = src[e1]; }
    atomicAdd(&sh[et0], 1);
    atomicAdd(&g_dcnt[d0], 1);
    if (p1) { atomicAdd(&sh[et1], 1); atomicAdd(&g_dcnt[d1], 1); }
    __syncthreads();
    for (int r = t; r < R; r += 256) g_bh[r * NB + blk] = sh[r];

    grid_barrier(&g_cntA, &g_genA, NB);

    // ---- phase 2: scans (block 0: dst, block 1: etype — in parallel) ----
    if (blk == 0) {
        __shared__ int wtot[8], wbas[8];
        const int SEG = (N_NODES + 255) / 256;          // 79
        int lo = t * SEG, hi = min(lo + SEG, N_NODES);
        int lsum = 0;
        for (int i = lo; i < hi; i++) lsum += g_dcnt[i];
        int s = lsum;
#pragma unroll
        for (int d = 1; d < 32; d <<= 1) {
            int x = __shfl_up_sync(FULL, s, d);
            if (lane >= d) s += x;
        }
        if (lane == 31) wtot[wid] = s;
        __syncthreads();
        if (wid == 0 && lane < 8) {
            int v = wtot[lane], s2 = v;
#pragma unroll
            for (int d = 1; d < 8; d <<= 1) {
                int x = __shfl_up_sync(0xffu, s2, d);
                if (lane >= d) s2 += x;
            }
            wbas[lane] = s2 - v;
            if (lane == 7) g_doff[N_NODES] = s2;
        }
        __syncthreads();
        int run = wbas[wid] + (s - lsum);
        for (int i = lo; i < hi; i++) {
            int v = g_dcnt[i];
            g_doff[i] = run; g_dcur[i] = run; run += v;
            g_dcnt[i] = 0;                               // self-zero for replay
        }
    } else if (blk == 1) {
        __shared__ int sh_hist[R];
        for (int r = wid; r < R; r += 8) {               // 8 warps
            const int CPL = (NB + 31) / 32;              // 13
            int v[CPL], pre[CPL], tot[CPL];
#pragma unroll
            for (int j = 0; j < CPL; j++) {
                int b = j * 32 + lane;
                v[j] = (b < NB) ? g_bh[r * NB + b] : 0;
            }
#pragma unroll
            for (int j = 0; j < CPL; j++) {
                int s = v[j];
#pragma unroll
                for (int d = 1; d < 32; d <<= 1) {
                    int x = __shfl_up_sync(FULL, s, d);
                    if (lane >= d) s += x;
                }
                pre[j] = s - v[j];
                tot[j] = __shfl_sync(FULL, s, 31);
            }
            int bacc = 0;
#pragma unroll
            for (int j = 0; j < CPL; j++) {
                int b = j * 32 + lane;
                if (b < NB) g_boff[r * NB + b] = bacc + pre[j];  // local
                bacc += tot[j];
            }
            if (lane == 0) sh_hist[r] = bacc;
        }
        __syncthreads();
        if (wid == 0) {                                  // relation-base scan
            int acc = 0, cacc = 0;
            for (int b0 = 0; b0 < R; b0 += 32) {
                int r = b0 + lane;
                int hv = (r < R) ? sh_hist[r] : 0;
                int cv = (hv + 31) >> 5;
                int hs = hv, cs = cv;
#pragma unroll
                for (int d = 1; d < 32; d <<= 1) {
                    int x1 = __shfl_up_sync(FULL, hs, d);
                    int x2 = __shfl_up_sync(FULL, cs, d);
                    if (lane >= d) { hs += x1; cs += x2; }
                }
                if (r < R) {
                    g_off[r] = acc + hs - hv;
                    g_chunkbase[r] = cacc + cs - cv;
                }
                acc  += __shfl_sync(FULL, hs, 31);
                cacc += __shfl_sync(FULL, cs, 31);
            }
            if (lane == 0) {
                g_off[R] = acc; g_chunkbase[R] = cacc; g_nchunk = cacc;
            }
        }
    }

    grid_barrier(&g_cntA, &g_genA, NB);

    // ---- phase 3: scatter (cursor = local boff + relation base) ----
    for (int r = t; r < R; r += 256)
        sh[r] = g_boff[r * NB + blk] + g_off[r];
    __syncthreads();
    int pos0 = atomicAdd(&sh[et0], 1);
    int dp0  = atomicAdd(&g_dcur[d0], 1);
    g_ssrc[pos0] = s0;
    g_dpos[pos0] = dp0;
    if (p1) {
        int pos1 = atomicAdd(&sh[et1], 1);
        int dp1  = atomicAdd(&g_dcur[d1], 1);
        g_ssrc[pos1] = s1;
        g_dpos[pos1] = dp1;
    }
}

// ============== KB: GEMV (f32x2) + stats + barrier + reduce ==============
__global__ void __launch_bounds__(128, 7) kb_compute(
    const float* __restrict__ h, const float* __restrict__ weight,
    const float* __restrict__ gamma, const float* __restrict__ beta,
    float* __restrict__ out)
{
    __shared__ __align__(16) float tile[4][32][32];
    __shared__ int s_cb[R + 1], s_off[R + 1];
    __shared__ float ssum[4][32], ssq[4][32];
    __shared__ float s_sc[32], s_sh[32];
    const int lane = threadIdx.x & 31;
    const int wid  = threadIdx.x >> 5;
    const int warp = (blockIdx.x * blockDim.x + threadIdx.x) >> 5;
    const int nwarp = (KB_BLOCKS * 128) >> 5;            // 4144

    for (int i = threadIdx.x; i <= R; i += blockDim.x) {
        s_cb[i] = g_chunkbase[i];
        s_off[i] = g_off[i];
    }
    __syncthreads();
    const int nchunk = g_nchunk;

    float lsum = 0.f, lsq = 0.f;
    int c0 = (int)((long long)warp * nchunk / nwarp);
    int c1 = (int)((long long)(warp + 1) * nchunk / nwarp);

    if (c0 < c1) {
        int lo2 = 0, hi2 = R;
        while (lo2 < hi2) {
            int mid = (lo2 + hi2 + 1) >> 1;
            if (s_cb[mid] <= c0) lo2 = mid; else hi2 = mid - 1;
        }
        int r = lo2;
        bool needW = true;
        unsigned long long wc2[16];

        for (int c = c0; c < c1; c++) {
            while (s_cb[r + 1] <= c) { r++; needW = true; }
            if (needW) {
                const float* wp = weight + r * (D * D) + lane;
#pragma unroll
                for (int k = 0; k < 16; k++) {
                    float w0 = wp[(2 * k) * 32];
                    float w1 = wp[(2 * k + 1) * 32];
                    asm("mov.b64 %0, {%1, %2};" : "=l"(wc2[k]) : "f"(w0), "f"(w1));
                }
                needW = false;
            }
            int s = s_off[r] + ((c - s_cb[r]) << 5);
            int n = min(32, s_off[r + 1] - s);

            int sj = 0, dj = 0;
            if (lane < n) { sj = g_ssrc[s + lane]; dj = g_dpos[s + lane]; }
            for (int j = 0; j < n; j++) {
                int sje = __shfl_sync(FULL, sj, j);
                tile[wid][j][lane] = h[sje * D + lane];  // coalesced 128B
            }
            __syncwarp();

            for (int j = 0; j < n; j++) {
                const ulonglong2* row = (const ulonglong2*)tile[wid][j];
                unsigned long long a0 = 0ull, a1 = 0ull, a2 = 0ull, a3 = 0ull;
#pragma unroll
                for (int kk = 0; kk < 8; kk += 2) {
                    ulonglong2 q0 = row[kk];             // LDS.128 broadcast
                    ulonglong2 q1 = row[kk + 1];
                    asm("fma.rn.f32x2 %0, %1, %2, %0;" : "+l"(a0) : "l"(q0.x), "l"(wc2[2 * kk + 0]));
                    asm("fma.rn.f32x2 %0, %1, %2, %0;" : "+l"(a1) : "l"(q0.y), "l"(wc2[2 * kk + 1]));
                    asm("fma.rn.f32x2 %0, %1, %2, %0;" : "+l"(a2) : "l"(q1.x), "l"(wc2[2 * kk + 2]));
                    asm("fma.rn.f32x2 %0, %1, %2, %0;" : "+l"(a3) : "l"(q1.y), "l"(wc2[2 * kk + 3]));
                }
                unsigned long long s01, s23, sT;
                asm("add.rn.f32x2 %0, %1, %2;" : "=l"(s01) : "l"(a0), "l"(a1));
                asm("add.rn.f32x2 %0, %1, %2;" : "=l"(s23) : "l"(a2), "l"(a3));
                asm("add.rn.f32x2 %0, %1, %2;" : "=l"(sT)  : "l"(s01), "l"(s23));
                float xlo, xhi;
                asm("mov.b64 {%0, %1}, %2;" : "=f"(xlo), "=f"(xhi) : "l"(sT));
                float acc = fmaxf(xlo + xhi, 0.f);
                lsum += acc;
                lsq = fmaf(acc, acc, lsq);
                g_msg[__shfl_sync(FULL, dj, j) * D + lane] = acc;
            }
            __syncwarp();
        }
    }

    // block-level stat reduce, one warp does global atomics
    ssum[wid][lane] = lsum; ssq[wid][lane] = lsq;
    __syncthreads();
    if (wid == 0) {
        float ts = ssum[0][lane] + ssum[1][lane] + ssum[2][lane] + ssum[3][lane];
        float tq = ssq[0][lane] + ssq[1][lane] + ssq[2][lane] + ssq[3][lane];
        atomicAdd(&g_sum[lane], ts);
        atomicAdd(&g_sumsq[lane], tq);
    }

    grid_barrier(&g_cntB, &g_genB, KB_BLOCKS);

    // ---- fused reduce: BN affine + per-node segment mean ----
    if (threadIdx.x < 32) {
        int d = threadIdx.x;
        float inv_e = 1.0f / (float)N_EDGES;
        float mu = g_sum[d] * inv_e;
        float var = fmaxf(g_sumsq[d] * inv_e - mu * mu, 0.f);
        float scale = rsqrtf(var + EPS) * gamma[d];
        s_sc[d] = scale;
        s_sh[d] = beta[d] - mu * scale;
    }
    __syncthreads();
    const float sc = s_sc[lane], shf = s_sh[lane];

    for (int node = warp; node < N_NODES; node += nwarp) {
        int off = g_doff[node], end = g_doff[node + 1];
        int cnt = end - off;
        float acc = 0.f;
        const float* p = g_msg + (size_t)off * D + lane;
        int i = 0;
#pragma unroll 4
        for (; i + 4 <= cnt; i += 4) {
            float v0 = p[(i + 0) * D];
            float v1 = p[(i + 1) * D];
            float v2 = p[(i + 2) * D];
            float v3 = p[(i + 3) * D];
            acc += (v0 + v1) + (v2 + v3);
        }
        for (; i < cnt; i++) acc += p[i * D];
        float v = 0.f;
        if (cnt > 0) v = fmaf(acc * (1.0f / (float)cnt), sc, shf);
        out[node * D + lane] = v;
    }
}

extern "C" void kernel_launch(void* const* d_in, const int* in_sizes, int n_in,
                              void* d_out, int out_size) {
    const float* h      = (const float*)d_in[0];
    const float* weight = (const float*)d_in[1];
    const float* gamma  = (const float*)d_in[2];
    const float* beta   = (const float*)d_in[3];
    const int*   src    = (const int*)d_in[4];
    const int*   dst    = (const int*)d_in[5];
    const int*   etype  = (const int*)d_in[6];
    float* out = (float*)d_out;

    ka_sort<<<NB, 256>>>(etype, src, dst);
    kb_compute<<<KB_BLOCKS, 128>>>(h, weight, gamma, beta, out);
}

// round 9
// speedup vs baseline: 1.0687x; 1.0548x over previous
#include <cuda_runtime.h>

#define N_NODES 20000
#define N_EDGES 200000
#define D 32
#define R 100
#define EPS 1e-5f
#define NB 400          // histogram/scatter blocks
#define EPB 500         // edges per block (NB*EPB == N_EDGES)
#define FULL 0xffffffffu

// ---------------- device scratch (static, no runtime allocation) --------
__device__ int   g_dcnt[N_NODES];           // per-dst edge counts
__device__ int   g_doff[N_NODES + 1];       // CSR offsets by dst
__device__ int   g_dcur[N_NODES];           // scatter cursors by dst
__device__ int   g_bh[R * NB];              // per-(relation, block) histogram
__device__ int   g_boff[R * NB];            // per-(relation, block) base offset
__device__ int   g_hist[R];                 // per-relation totals
__device__ int   g_off[R + 1];              // exclusive scan of g_hist
__device__ int   g_chunkbase[R + 1];        // exclusive scan of chunk counts
__device__ int   g_ssrc[N_EDGES];           // src sorted by etype
__device__ int   g_eidx2[N_EDGES];          // msg-positions grouped by dst
__device__ float g_msg[N_EDGES * D];        // relu(h[src] @ W[etype]), etype order
__device__ float g_sum[D], g_sumsq[D];
__device__ float g_scale[D], g_shift[D];
__device__ int   g_nchunk;

// ---------------- K0: zero per-call accumulators ----------------
__global__ void k0_zero() {
    int i = blockIdx.x * blockDim.x + threadIdx.x;
    int stride = gridDim.x * blockDim.x;
    for (int j = i; j < N_NODES; j += stride) g_dcnt[j] = 0;
    if (i < D) { g_sum[i] = 0.f; g_sumsq[i] = 0.f; }
}

// ---------------- K1: per-block etype histograms + global dst histogram --
__global__ void __launch_bounds__(256) k1_hist(const int* __restrict__ etype,
                                               const int* __restrict__ dst) {
    __shared__ int sh[R];
    for (int i = threadIdx.x; i < R; i += blockDim.x) sh[i] = 0;
    __syncthreads();
    int base = blockIdx.x * EPB;
    for (int i = threadIdx.x; i < EPB; i += blockDim.x) {
        atomicAdd(&sh[etype[base + i]], 1);
        atomicAdd(&g_dcnt[dst[base + i]], 1);   // 20K spread addrs: cheap
    }
    __syncthreads();
    for (int r = threadIdx.x; r < R; r += blockDim.x)
        g_bh[r * NB + blockIdx.x] = sh[r];
}

// ---------------- K2: etype scans, fully warp-parallel (1 block) ---------
__global__ void __launch_bounds__(1024) k2_scan() {
    const int lane = threadIdx.x & 31;
    const int wid  = threadIdx.x >> 5;   // 0..31

    // phase 1: per-relation totals (warp-per-relation coalesced reduce)
    for (int r = wid; r < R; r += 32) {
        int s = 0;
        for (int b = lane; b < NB; b += 32) s += g_bh[r * NB + b];
#pragma unroll
        for (int d = 16; d > 0; d >>= 1) s += __shfl_down_sync(FULL, s, d);
        if (lane == 0) g_hist[r] = s;
    }
    __syncthreads();

    // phase 2: scan relation totals + chunk counts (warp 0, shfl scans)
    if (wid == 0) {
        int acc = 0, cacc = 0;
        for (int base = 0; base < R; base += 32) {
            int r = base + lane;
            int hv = (r < R) ? g_hist[r] : 0;
            int cv = (hv + 31) >> 5;
            int hs = hv, cs = cv;
#pragma unroll
            for (int d = 1; d < 32; d <<= 1) {
                int t1 = __shfl_up_sync(FULL, hs, d);
                int t2 = __shfl_up_sync(FULL, cs, d);
                if (lane >= d) { hs += t1; cs += t2; }
            }
            if (r < R) {
                g_off[r] = acc + hs - hv;
                g_chunkbase[r] = cacc + cs - cv;
            }
            acc  += __shfl_sync(FULL, hs, 31);
            cacc += __shfl_sync(FULL, cs, 31);
        }
        if (lane == 0) { g_off[R] = acc; g_chunkbase[R] = cacc; g_nchunk = cacc; }
    }
    __syncthreads();

    // phase 3: per-relation scan over blocks (warp-per-relation, shfl scan)
    for (int r = wid; r < R; r += 32) {
        int carry = g_off[r];
        for (int b0 = 0; b0 < NB; b0 += 32) {
            int b = b0 + lane;
            int v = (b < NB) ? g_bh[r * NB + b] : 0;
            int s = v;
#pragma unroll
            for (int d = 1; d < 32; d <<= 1) {
                int t = __shfl_up_sync(FULL, s, d);
                if (lane >= d) s += t;
            }
            if (b < NB) g_boff[r * NB + b] = carry + s - v;
            carry += __shfl_sync(FULL, s, 31);
        }
    }
}

// ---------------- K2b: dst-offset scan, REGISTER-BATCHED (1 block) -------
// Each thread loads its 20 elements up-front (MLP=20), local prefix in
// registers, one warp scan + one cross-warp scan, batched write-back.
// Replaces the 20.4us serial-carry version measured in round 4.
__global__ void __launch_bounds__(1024) k2b_dscan() {
    __shared__ int wsum[32], wbase[32];
    const int lane = threadIdx.x & 31;
    const int wid  = threadIdx.x >> 5;
    const int tid  = threadIdx.x;

    const int NPT = 20;                       // 1024*20 >= 20000
    int base_i = tid * NPT;
    int v[NPT];
    int lsum = 0;
#pragma unroll
    for (int j = 0; j < NPT; j++) {
        int i = base_i + j;
        v[j] = (i < N_NODES) ? g_dcnt[i] : 0; // batched loads, MLP=20
        lsum += v[j];
    }
    int s = lsum;
#pragma unroll
    for (int d = 1; d < 32; d <<= 1) {
        int t = __shfl_up_sync(FULL, s, d);
        if (lane >= d) s += t;
    }
    int excl = s - lsum;
    if (lane == 31) wsum[wid] = s;
    __syncthreads();
    if (wid == 0) {
        int v2 = wsum[lane], s2 = v2;
#pragma unroll
        for (int d = 1; d < 32; d <<= 1) {
            int t = __shfl_up_sync(FULL, s2, d);
            if (lane >= d) s2 += t;
        }
        wbase[lane] = s2 - v2;
        if (lane == 31) g_doff[N_NODES] = s2;
    }
    __syncthreads();
    int run = wbase[wid] + excl;
#pragma unroll
    for (int j = 0; j < NPT; j++) {
        int i = base_i + j;
        if (i < N_NODES) { g_doff[i] = run; g_dcur[i] = run; run += v[j]; }
    }
}

// ---------------- K3: dual scatter (etype perm + dst perm) ----------------
__global__ void __launch_bounds__(256) k3_scatter(
    const int* __restrict__ etype, const int* __restrict__ src,
    const int* __restrict__ dst)
{
    __shared__ int cur[R];
    for (int r = threadIdx.x; r < R; r += blockDim.x)
        cur[r] = g_boff[r * NB + blockIdx.x];
    __syncthreads();
    int base = blockIdx.x * EPB;
    for (int i = threadIdx.x; i < EPB; i += blockDim.x) {
        int e = base + i;
        int pos = atomicAdd(&cur[etype[e]], 1);    // shared, low contention
        g_ssrc[pos] = src[e];
        int dpos = atomicAdd(&g_dcur[dst[e]], 1);  // 20K spread addrs
        g_eidx2[dpos] = pos;
    }
}

// ---------------- K4: GEMV pass — shared h-tile, LDS.128 broadcast --------
// One warp = one 32-edge chunk of one relation (found by binary search in
// shared chunkbase table). Lane d holds column d of W[r] in registers.
__global__ void __launch_bounds__(128) k4_compute(
    const float* __restrict__ h, const float* __restrict__ weight)
{
    __shared__ float tile[4][32][32];
    __shared__ int s_cb[R + 1], s_off[R + 1];
    const int lane = threadIdx.x & 31;
    const int wid  = threadIdx.x >> 5;
    const int warp = (blockIdx.x * blockDim.x + threadIdx.x) >> 5;
    const int nwarp = (gridDim.x * blockDim.x) >> 5;

    for (int i = threadIdx.x; i <= R; i += blockDim.x) {
        s_cb[i] = g_chunkbase[i];
        s_off[i] = g_off[i];
    }
    __syncthreads();
    const int nchunk = g_nchunk;

    float lsum = 0.f, lsq = 0.f;

    for (int w = warp; w < nchunk; w += nwarp) {
        // largest r with chunkbase[r] <= w
        int lo2 = 0, hi2 = R;
        while (lo2 < hi2) {
            int mid = (lo2 + hi2 + 1) >> 1;
            if (s_cb[mid] <= w) lo2 = mid; else hi2 = mid - 1;
        }
        int r = lo2;
        int s = s_off[r] + ((w - s_cb[r]) << 5);
        int n = min(32, s_off[r + 1] - s);

        const float* wp = weight + r * (D * D) + lane;
        float wc[32];
#pragma unroll
        for (int k = 0; k < 32; k++) wc[k] = wp[k * 32];

        int sj = 0;
        if (lane < n) sj = g_ssrc[s + lane];
        for (int j = 0; j < n; j++) {
            int sje = __shfl_sync(FULL, sj, j);
            tile[wid][j][lane] = h[sje * D + lane];   // coalesced 128B
        }
        __syncwarp();

        for (int j = 0; j < n; j++) {
            const float4* row = (const float4*)tile[wid][j];
            float a0 = 0.f, a1 = 0.f, a2 = 0.f, a3 = 0.f;
#pragma unroll
            for (int kk = 0; kk < 8; kk++) {
                float4 hq = row[kk];                  // 16B broadcast LDS
                a0 = fmaf(hq.x, wc[4 * kk + 0], a0);
                a1 = fmaf(hq.y, wc[4 * kk + 1], a1);
                a2 = fmaf(hq.z, wc[4 * kk + 2], a2);
                a3 = fmaf(hq.w, wc[4 * kk + 3], a3);
            }
            float acc = fmaxf((a0 + a1) + (a2 + a3), 0.f);
            lsum += acc;
            lsq = fmaf(acc, acc, lsq);
            g_msg[(s + j) * D + lane] = acc;          // coalesced 128B store
        }
        __syncwarp();
    }
    __shared__ float ssum[4][32], ssq[4][32];
    ssum[wid][lane] = lsum; ssq[wid][lane] = lsq;
    __syncthreads();
    if (wid == 0) {
        float ts = ssum[0][lane] + ssum[1][lane] + ssum[2][lane] + ssum[3][lane];
        float tq = ssq[0][lane] + ssq[1][lane] + ssq[2][lane] + ssq[3][lane];
        atomicAdd(&g_sum[lane], ts);
        atomicAdd(&g_sumsq[lane], tq);
    }
}

// ---------------- K5: fold batchnorm into affine scale/shift -------------
__global__ void k5_final(const float* __restrict__ gamma,
                         const float* __restrict__ beta) {
    int d = threadIdx.x;
    if (d < D) {
        float inv_e = 1.0f / (float)N_EDGES;
        float mu = g_sum[d] * inv_e;
        float var = fmaxf(g_sumsq[d] * inv_e - mu * mu, 0.f);
        float scale = rsqrtf(var + EPS) * gamma[d];
        g_scale[d] = scale;
        g_shift[d] = beta[d] - mu * scale;
    }
}

// ---------------- K6: warp-per-node gather reduce (atomic-free) ----------
__global__ void __launch_bounds__(128) k6_reduce(float* __restrict__ out) {
    const int lane = threadIdx.x & 31;
    const int node = (blockIdx.x * blockDim.x + threadIdx.x) >> 5;
    if (node >= N_NODES) return;
    const float sc = g_scale[lane], shf = g_shift[lane];

    int off = g_doff[node], end = g_doff[node + 1];
    int cnt = end - off;
    float acc = 0.f;
    int i = off;
    for (; i + 1 < end; i += 2) {
        int p0 = g_eidx2[i];
        int p1 = g_eidx2[i + 1];
        acc += g_msg[p0 * D + lane];
        acc += g_msg[p1 * D + lane];
    }
    if (i < end) acc += g_msg[g_eidx2[i] * D + lane];

    float v = 0.f;
    if (cnt > 0) v = fmaf(acc * (1.0f / (float)cnt), sc, shf);
    out[node * D + lane] = v;
}

extern "C" void kernel_launch(void* const* d_in, const int* in_sizes, int n_in,
                              void* d_out, int out_size) {
    const float* h      = (const float*)d_in[0];
    const float* weight = (const float*)d_in[1];
    const float* gamma  = (const float*)d_in[2];
    const float* beta   = (const float*)d_in[3];
    const int*   src    = (const int*)d_in[4];
    const int*   dst    = (const int*)d_in[5];
    const int*   etype  = (const int*)d_in[6];
    float* out = (float*)d_out;

    k0_zero<<<160, 128>>>();
    k1_hist<<<NB, 256>>>(etype, dst);
    k2_scan<<<1, 1024>>>();
    k2b_dscan<<<1, 1024>>>();
    k3_scatter<<<NB, 256>>>(etype, src, dst);
    k4_compute<<<1600, 128>>>(h, weight);
    k5_final<<<1, 32>>>(gamma, beta);
    k6_reduce<<<(N_NODES * 32 + 127) / 128, 128>>>(out);
}

// round 10
// speedup vs baseline: 1.1768x; 1.1012x over previous
#include <cuda_runtime.h>

#define N_NODES 20000
#define N_EDGES 200000
#define D 32
#define R 100
#define EPS 1e-5f
#define NB 400          // histogram/scatter blocks
#define EPB 500         // edges per block (NB*EPB == N_EDGES)
#define FULL 0xffffffffu

// ---------------- device scratch (static, no runtime allocation) --------
__device__ int   g_dcnt[N_NODES];           // per-dst counts (self-zeroing)
__device__ int   g_doff[N_NODES + 1];       // CSR offsets by dst
__device__ int   g_dcur[N_NODES];           // scatter cursors by dst
__device__ int   g_bh[R * NB];              // per-(relation, block) histogram
__device__ int   g_boff[R * NB];            // per-(relation, block) base offset
__device__ int   g_hist[R];                 // per-relation totals
__device__ int   g_off[R + 1];              // exclusive scan of g_hist
__device__ int   g_chunkbase[R + 1];        // exclusive scan of chunk counts
__device__ int   g_ssrc[N_EDGES];           // src sorted by etype
__device__ int   g_eidx2[N_EDGES];          // msg-positions grouped by dst
__device__ float g_msg[N_EDGES * D];        // relu(h[src] @ W[etype]), etype order
__device__ float g_sum[D], g_sumsq[D];
__device__ int   g_nchunk;

// ---------------- K1: per-block etype histograms + global dst histogram --
__global__ void __launch_bounds__(256) k1_hist(const int* __restrict__ etype,
                                               const int* __restrict__ dst) {
    __shared__ int sh[R];
    for (int i = threadIdx.x; i < R; i += blockDim.x) sh[i] = 0;
    __syncthreads();
    int base = blockIdx.x * EPB;
    for (int i = threadIdx.x; i < EPB; i += blockDim.x) {
        atomicAdd(&sh[etype[base + i]], 1);
        atomicAdd(&g_dcnt[dst[base + i]], 1);   // 20K spread addrs: cheap
    }
    __syncthreads();
    for (int r = threadIdx.x; r < R; r += blockDim.x)
        g_bh[r * NB + blockIdx.x] = sh[r];
}

// ---------------- KS: both scans in one kernel, 2 independent blocks -----
// block 0: etype scans (relation totals, bases, per-block offsets)
// block 1: dst-count scan (two-pass, spill-free) + zero g_sum/g_sumsq
__global__ void __launch_bounds__(1024) ks_scan() {
    __shared__ int wsum[32], wbase[32];
    const int lane = threadIdx.x & 31;
    const int wid  = threadIdx.x >> 5;
    const int tid  = threadIdx.x;

    if (blockIdx.x == 0) {
        // ---- phase 1: per-relation totals (warp-per-relation reduce) ----
        for (int r = wid; r < R; r += 32) {
            int s = 0;
            for (int b = lane; b < NB; b += 32) s += g_bh[r * NB + b];
#pragma unroll
            for (int d = 16; d > 0; d >>= 1) s += __shfl_down_sync(FULL, s, d);
            if (lane == 0) g_hist[r] = s;
        }
        __syncthreads();

        // ---- phase 2: scan relation totals + chunk counts (warp 0) ----
        if (wid == 0) {
            int acc = 0, cacc = 0;
            for (int base = 0; base < R; base += 32) {
                int r = base + lane;
                int hv = (r < R) ? g_hist[r] : 0;
                int cv = (hv + 31) >> 5;
                int hs = hv, cs = cv;
#pragma unroll
                for (int d = 1; d < 32; d <<= 1) {
                    int t1 = __shfl_up_sync(FULL, hs, d);
                    int t2 = __shfl_up_sync(FULL, cs, d);
                    if (lane >= d) { hs += t1; cs += t2; }
                }
                if (r < R) {
                    g_off[r] = acc + hs - hv;
                    g_chunkbase[r] = cacc + cs - cv;
                }
                acc  += __shfl_sync(FULL, hs, 31);
                cacc += __shfl_sync(FULL, cs, 31);
            }
            if (lane == 0) { g_off[R] = acc; g_chunkbase[R] = cacc; g_nchunk = cacc; }
        }
        __syncthreads();

        // ---- phase 3: per-relation scan over blocks (warp/relation) ----
        for (int r = wid; r < R; r += 32) {
            int carry = g_off[r];
            for (int b0 = 0; b0 < NB; b0 += 32) {
                int b = b0 + lane;
                int v = (b < NB) ? g_bh[r * NB + b] : 0;
                int s = v;
#pragma unroll
                for (int d = 1; d < 32; d <<= 1) {
                    int t = __shfl_up_sync(FULL, s, d);
                    if (lane >= d) s += t;
                }
                if (b < NB) g_boff[r * NB + b] = carry + s - v;
                carry += __shfl_sync(FULL, s, 31);
            }
        }
    } else {
        // ================= block 1: dst scan, TWO-PASS (no reg array) ====
        if (tid < D) { g_sum[tid] = 0.f; g_sumsq[tid] = 0.f; }

        const int NPT = 20;                       // 1024*20 >= 20000
        int base_i = tid * NPT;
        // pass 1: sum only (20 independent loads, no array -> no spills)
        int lsum = 0;
#pragma unroll
        for (int j = 0; j < NPT; j++) {
            int i = base_i + j;
            if (i < N_NODES) lsum += g_dcnt[i];
        }
        int s = lsum;
#pragma unroll
        for (int d = 1; d < 32; d <<= 1) {
            int t = __shfl_up_sync(FULL, s, d);
            if (lane >= d) s += t;
        }
        int excl = s - lsum;
        if (lane == 31) wsum[wid] = s;
        __syncthreads();
        if (wid == 0) {
            int v2 = wsum[lane], s2 = v2;
#pragma unroll
            for (int d = 1; d < 32; d <<= 1) {
                int t = __shfl_up_sync(FULL, s2, d);
                if (lane >= d) s2 += t;
            }
            wbase[lane] = s2 - v2;
            if (lane == 31) g_doff[N_NODES] = s2;
        }
        __syncthreads();
        // pass 2: reload values (L2 hits, independent of carry), write, zero
        int run = wbase[wid] + excl;
#pragma unroll
        for (int j = 0; j < NPT; j++) {
            int i = base_i + j;
            if (i < N_NODES) {
                int v = g_dcnt[i];
                g_doff[i] = run;
                g_dcur[i] = run;
                g_dcnt[i] = 0;                    // self-zero for next replay
                run += v;
            }
        }
    }
}

// ---------------- K3: dual scatter (etype perm + dst perm) ----------------
__global__ void __launch_bounds__(256) k3_scatter(
    const int* __restrict__ etype, const int* __restrict__ src,
    const int* __restrict__ dst)
{
    __shared__ int cur[R];
    for (int r = threadIdx.x; r < R; r += blockDim.x)
        cur[r] = g_boff[r * NB + blockIdx.x];
    __syncthreads();
    int base = blockIdx.x * EPB;
    for (int i = threadIdx.x; i < EPB; i += blockDim.x) {
        int e = base + i;
        int pos = atomicAdd(&cur[etype[e]], 1);    // shared, low contention
        g_ssrc[pos] = src[e];
        int dpos = atomicAdd(&g_dcur[dst[e]], 1);  // 20K spread addrs
        g_eidx2[dpos] = pos;
    }
}

// ---------------- K4: GEMV pass — shared h-tile, LDS.128 broadcast --------
// One warp = one 32-edge chunk of one relation (binary search in shared
// chunkbase table). Lane d holds column d of W[r] in registers.
__global__ void __launch_bounds__(128) k4_compute(
    const float* __restrict__ h, const float* __restrict__ weight)
{
    __shared__ float tile[4][32][32];
    __shared__ int s_cb[R + 1], s_off[R + 1];
    const int lane = threadIdx.x & 31;
    const int wid  = threadIdx.x >> 5;
    const int warp = (blockIdx.x * blockDim.x + threadIdx.x) >> 5;
    const int nwarp = (gridDim.x * blockDim.x) >> 5;

    for (int i = threadIdx.x; i <= R; i += blockDim.x) {
        s_cb[i] = g_chunkbase[i];
        s_off[i] = g_off[i];
    }
    __syncthreads();
    const int nchunk = g_nchunk;

    float lsum = 0.f, lsq = 0.f;

    for (int w = warp; w < nchunk; w += nwarp) {
        int lo2 = 0, hi2 = R;                      // largest r: cb[r] <= w
        while (lo2 < hi2) {
            int mid = (lo2 + hi2 + 1) >> 1;
            if (s_cb[mid] <= w) lo2 = mid; else hi2 = mid - 1;
        }
        int r = lo2;
        int s = s_off[r] + ((w - s_cb[r]) << 5);
        int n = min(32, s_off[r + 1] - s);

        const float* wp = weight + r * (D * D) + lane;
        float wc[32];
#pragma unroll
        for (int k = 0; k < 32; k++) wc[k] = wp[k * 32];

        int sj = 0;
        if (lane < n) sj = g_ssrc[s + lane];
        for (int j = 0; j < n; j++) {
            int sje = __shfl_sync(FULL, sj, j);
            tile[wid][j][lane] = h[sje * D + lane];   // coalesced 128B
        }
        __syncwarp();

        for (int j = 0; j < n; j++) {
            const float4* row = (const float4*)tile[wid][j];
            float a0 = 0.f, a1 = 0.f, a2 = 0.f, a3 = 0.f;
#pragma unroll
            for (int kk = 0; kk < 8; kk++) {
                float4 hq = row[kk];                  // 16B broadcast LDS
                a0 = fmaf(hq.x, wc[4 * kk + 0], a0);
                a1 = fmaf(hq.y, wc[4 * kk + 1], a1);
                a2 = fmaf(hq.z, wc[4 * kk + 2], a2);
                a3 = fmaf(hq.w, wc[4 * kk + 3], a3);
            }
            float acc = fmaxf((a0 + a1) + (a2 + a3), 0.f);
            lsum += acc;
            lsq = fmaf(acc, acc, lsq);
            g_msg[(s + j) * D + lane] = acc;          // coalesced 128B store
        }
        __syncwarp();
    }
    __shared__ float ssum[4][32], ssq[4][32];
    ssum[wid][lane] = lsum; ssq[wid][lane] = lsq;
    __syncthreads();
    if (wid == 0) {
        float ts = ssum[0][lane] + ssum[1][lane] + ssum[2][lane] + ssum[3][lane];
        float tq = ssq[0][lane] + ssq[1][lane] + ssq[2][lane] + ssq[3][lane];
        atomicAdd(&g_sum[lane], ts);
        atomicAdd(&g_sumsq[lane], tq);
    }
}

// ---------------- K6: gather reduce + folded BN finalize -----------------
__global__ void __launch_bounds__(128) k6_reduce(
    float* __restrict__ out, const float* __restrict__ gamma,
    const float* __restrict__ beta)
{
    __shared__ float s_sc[32], s_sh[32];
    if (threadIdx.x < 32) {
        int d = threadIdx.x;
        float inv_e = 1.0f / (float)N_EDGES;
        float mu = g_sum[d] * inv_e;
        float var = fmaxf(g_sumsq[d] * inv_e - mu * mu, 0.f);
        float scale = rsqrtf(var + EPS) * gamma[d];
        s_sc[d] = scale;
        s_sh[d] = beta[d] - mu * scale;
    }
    __syncthreads();

    const int lane = threadIdx.x & 31;
    const int node = (blockIdx.x * blockDim.x + threadIdx.x) >> 5;
    if (node >= N_NODES) return;
    const float sc = s_sc[lane], shf = s_sh[lane];

    int off = g_doff[node], end = g_doff[node + 1];
    int cnt = end - off;
    float acc = 0.f;
    int i = off;
    for (; i + 1 < end; i += 2) {
        int p0 = g_eidx2[i];
        int p1 = g_eidx2[i + 1];
        acc += g_msg[p0 * D + lane];
        acc += g_msg[p1 * D + lane];
    }
    if (i < end) acc += g_msg[g_eidx2[i] * D + lane];

    float v = 0.f;
    if (cnt > 0) v = fmaf(acc * (1.0f / (float)cnt), sc, shf);
    out[node * D + lane] = v;
}

extern "C" void kernel_launch(void* const* d_in, const int* in_sizes, int n_in,
                              void* d_out, int out_size) {
    const float* h      = (const float*)d_in[0];
    const float* weight = (const float*)d_in[1];
    const float* gamma  = (const float*)d_in[2];
    const float* beta   = (const float*)d_in[3];
    const int*   src    = (const int*)d_in[4];
    const int*   dst    = (const int*)d_in[5];
    const int*   etype  = (const int*)d_in[6];
    float* out = (float*)d_out;

    k1_hist<<<NB, 256>>>(etype, dst);
    ks_scan<<<2, 1024>>>();
    k3_scatter<<<NB, 256>>>(etype, src, dst);
    k4_compute<<<1600, 128>>>(h, weight);
    k6_reduce<<<(N_NODES * 32 + 127) / 128, 128>>>(out, gamma, beta);
}

// round 11
// speedup vs baseline: 1.2346x; 1.0491x over previous
#include <cuda_runtime.h>

#define N_NODES 20000
#define N_EDGES 200000
#define D 32
#define R 100
#define EPS 1e-5f
#define NB 400          // histogram/scatter blocks
#define EPB 500         // edges per block (NB*EPB == N_EDGES)
#define FULL 0xffffffffu

// ---------------- device scratch (static, no runtime allocation) --------
__device__ int   g_dcnt[N_NODES];           // per-dst counts (self-zeroing)
__device__ int   g_doff[N_NODES + 1];       // CSR offsets by dst
__device__ int   g_dcur[N_NODES];           // scatter cursors by dst
__device__ int   g_bh[R * NB];              // per-(relation, block) histogram
__device__ int   g_boff[R * NB];            // per-(relation, block) base offset
__device__ int   g_hist[R];                 // per-relation totals
__device__ int   g_off[R + 1];              // exclusive scan of g_hist
__device__ int   g_chunkbase[R + 1];        // exclusive scan of chunk counts
__device__ int   g_ssrc[N_EDGES];           // src sorted by etype
__device__ int   g_eidx2[N_EDGES];          // msg-positions grouped by dst
__device__ float g_msg[N_EDGES * D];        // relu(h[src] @ W[etype]), etype order
__device__ float g_sum[D], g_sumsq[D];
__device__ int   g_nchunk;

// ---------------- K1: per-block etype histograms + global dst histogram --
__global__ void __launch_bounds__(256) k1_hist(const int* __restrict__ etype,
                                               const int* __restrict__ dst) {
    __shared__ int sh[R];
    for (int i = threadIdx.x; i < R; i += blockDim.x) sh[i] = 0;
    __syncthreads();
    int base = blockIdx.x * EPB;
    for (int i = threadIdx.x; i < EPB; i += blockDim.x) {
        atomicAdd(&sh[etype[base + i]], 1);
        atomicAdd(&g_dcnt[dst[base + i]], 1);   // 20K spread addrs: cheap
    }
    __syncthreads();
    for (int r = threadIdx.x; r < R; r += blockDim.x)
        g_bh[r * NB + blockIdx.x] = sh[r];
}

// ---------------- KS: both scans in one kernel, 2 independent blocks -----
// block 0: etype scans (relation totals, bases, per-block offsets)
// block 1: dst-count scan (two-pass, spill-free) + zero g_sum/g_sumsq
__global__ void __launch_bounds__(1024) ks_scan() {
    __shared__ int wsum[32], wbase[32];
    const int lane = threadIdx.x & 31;
    const int wid  = threadIdx.x >> 5;
    const int tid  = threadIdx.x;

    if (blockIdx.x == 0) {
        // ---- phase 1: per-relation totals (warp-per-relation reduce) ----
        for (int r = wid; r < R; r += 32) {
            int s = 0;
            for (int b = lane; b < NB; b += 32) s += g_bh[r * NB + b];
#pragma unroll
            for (int d = 16; d > 0; d >>= 1) s += __shfl_down_sync(FULL, s, d);
            if (lane == 0) g_hist[r] = s;
        }
        __syncthreads();

        // ---- phase 2: scan relation totals + chunk counts (warp 0) ----
        if (wid == 0) {
            int acc = 0, cacc = 0;
            for (int base = 0; base < R; base += 32) {
                int r = base + lane;
                int hv = (r < R) ? g_hist[r] : 0;
                int cv = (hv + 31) >> 5;
                int hs = hv, cs = cv;
#pragma unroll
                for (int d = 1; d < 32; d <<= 1) {
                    int t1 = __shfl_up_sync(FULL, hs, d);
                    int t2 = __shfl_up_sync(FULL, cs, d);
                    if (lane >= d) { hs += t1; cs += t2; }
                }
                if (r < R) {
                    g_off[r] = acc + hs - hv;
                    g_chunkbase[r] = cacc + cs - cv;
                }
                acc  += __shfl_sync(FULL, hs, 31);
                cacc += __shfl_sync(FULL, cs, 31);
            }
            if (lane == 0) { g_off[R] = acc; g_chunkbase[R] = cacc; g_nchunk = cacc; }
        }
        __syncthreads();

        // ---- phase 3: per-relation scan over blocks (warp/relation) ----
        for (int r = wid; r < R; r += 32) {
            int carry = g_off[r];
            for (int b0 = 0; b0 < NB; b0 += 32) {
                int b = b0 + lane;
                int v = (b < NB) ? g_bh[r * NB + b] : 0;
                int s = v;
#pragma unroll
                for (int d = 1; d < 32; d <<= 1) {
                    int t = __shfl_up_sync(FULL, s, d);
                    if (lane >= d) s += t;
                }
                if (b < NB) g_boff[r * NB + b] = carry + s - v;
                carry += __shfl_sync(FULL, s, 31);
            }
        }
    } else {
        // ================= block 1: dst scan, TWO-PASS (no reg array) ====
        if (tid < D) { g_sum[tid] = 0.f; g_sumsq[tid] = 0.f; }

        const int NPT = 20;                       // 1024*20 >= 20000
        int base_i = tid * NPT;
        // pass 1: sum only (20 independent loads, no array -> no spills)
        int lsum = 0;
#pragma unroll
        for (int j = 0; j < NPT; j++) {
            int i = base_i + j;
            if (i < N_NODES) lsum += g_dcnt[i];
        }
        int s = lsum;
#pragma unroll
        for (int d = 1; d < 32; d <<= 1) {
            int t = __shfl_up_sync(FULL, s, d);
            if (lane >= d) s += t;
        }
        int excl = s - lsum;
        if (lane == 31) wsum[wid] = s;
        __syncthreads();
        if (wid == 0) {
            int v2 = wsum[lane], s2 = v2;
#pragma unroll
            for (int d = 1; d < 32; d <<= 1) {
                int t = __shfl_up_sync(FULL, s2, d);
                if (lane >= d) s2 += t;
            }
            wbase[lane] = s2 - v2;
            if (lane == 31) g_doff[N_NODES] = s2;
        }
        __syncthreads();
        // pass 2: reload values (L2 hits, independent of carry), write, zero
        int run = wbase[wid] + excl;
#pragma unroll
        for (int j = 0; j < NPT; j++) {
            int i = base_i + j;
            if (i < N_NODES) {
                int v = g_dcnt[i];
                g_doff[i] = run;
                g_dcur[i] = run;
                g_dcnt[i] = 0;                    // self-zero for next replay
                run += v;
            }
        }
    }
}

// ---------------- K3: dual scatter (etype perm + dst perm) ----------------
__global__ void __launch_bounds__(256) k3_scatter(
    const int* __restrict__ etype, const int* __restrict__ src,
    const int* __restrict__ dst)
{
    __shared__ int cur[R];
    for (int r = threadIdx.x; r < R; r += blockDim.x)
        cur[r] = g_boff[r * NB + blockIdx.x];
    __syncthreads();
    int base = blockIdx.x * EPB;
    for (int i = threadIdx.x; i < EPB; i += blockDim.x) {
        int e = base + i;
        int pos = atomicAdd(&cur[etype[e]], 1);    // shared, low contention
        g_ssrc[pos] = src[e];
        int dpos = atomicAdd(&g_dcur[dst[e]], 1);  // 20K spread addrs
        g_eidx2[dpos] = pos;
    }
}

// ---------------- K4: GEMV pass — shared h-tile + packed FFMA2 ------------
// ONLY change vs the 80.0us kernel: inner loop uses fma.rn.f32x2, halving
// the FMA instruction stream (32 FFMA -> 16 FFMA2) in an issue-bound kernel.
__global__ void __launch_bounds__(128) k4_compute(
    const float* __restrict__ h, const float* __restrict__ weight)
{
    __shared__ __align__(16) float tile[4][32][32];
    __shared__ int s_cb[R + 1], s_off[R + 1];
    const int lane = threadIdx.x & 31;
    const int wid  = threadIdx.x >> 5;
    const int warp = (blockIdx.x * blockDim.x + threadIdx.x) >> 5;
    const int nwarp = (gridDim.x * blockDim.x) >> 5;

    for (int i = threadIdx.x; i <= R; i += blockDim.x) {
        s_cb[i] = g_chunkbase[i];
        s_off[i] = g_off[i];
    }
    __syncthreads();
    const int nchunk = g_nchunk;

    float lsum = 0.f, lsq = 0.f;

    for (int w = warp; w < nchunk; w += nwarp) {
        int lo2 = 0, hi2 = R;                      // largest r: cb[r] <= w
        while (lo2 < hi2) {
            int mid = (lo2 + hi2 + 1) >> 1;
            if (s_cb[mid] <= w) lo2 = mid; else hi2 = mid - 1;
        }
        int r = lo2;
        int s = s_off[r] + ((w - s_cb[r]) << 5);
        int n = min(32, s_off[r + 1] - s);

        // pack W columns for this lane into 16 b64 (f32x2) registers
        const float* wp = weight + r * (D * D) + lane;
        unsigned long long wc2[16];
#pragma unroll
        for (int k = 0; k < 16; k++) {
            float w0 = wp[(2 * k) * 32];
            float w1 = wp[(2 * k + 1) * 32];
            asm("mov.b64 %0, {%1, %2};" : "=l"(wc2[k]) : "f"(w0), "f"(w1));
        }

        int sj = 0;
        if (lane < n) sj = g_ssrc[s + lane];
        for (int j = 0; j < n; j++) {
            int sje = __shfl_sync(FULL, sj, j);
            tile[wid][j][lane] = h[sje * D + lane];   // coalesced 128B
        }
        __syncwarp();

        for (int j = 0; j < n; j++) {
            const ulonglong2* row = (const ulonglong2*)tile[wid][j];
            unsigned long long a0 = 0ull, a1 = 0ull, a2 = 0ull, a3 = 0ull;
#pragma unroll
            for (int kk = 0; kk < 4; kk++) {
                ulonglong2 q0 = row[2 * kk];          // LDS.128 broadcast
                ulonglong2 q1 = row[2 * kk + 1];
                asm("fma.rn.f32x2 %0, %1, %2, %0;" : "+l"(a0) : "l"(q0.x), "l"(wc2[4 * kk + 0]));
                asm("fma.rn.f32x2 %0, %1, %2, %0;" : "+l"(a1) : "l"(q0.y), "l"(wc2[4 * kk + 1]));
                asm("fma.rn.f32x2 %0, %1, %2, %0;" : "+l"(a2) : "l"(q1.x), "l"(wc2[4 * kk + 2]));
                asm("fma.rn.f32x2 %0, %1, %2, %0;" : "+l"(a3) : "l"(q1.y), "l"(wc2[4 * kk + 3]));
            }
            unsigned long long s01, s23, sT;
            asm("add.rn.f32x2 %0, %1, %2;" : "=l"(s01) : "l"(a0), "l"(a1));
            asm("add.rn.f32x2 %0, %1, %2;" : "=l"(s23) : "l"(a2), "l"(a3));
            asm("add.rn.f32x2 %0, %1, %2;" : "=l"(sT)  : "l"(s01), "l"(s23));
            float xlo, xhi;
            asm("mov.b64 {%0, %1}, %2;" : "=f"(xlo), "=f"(xhi) : "l"(sT));
            float acc = fmaxf(xlo + xhi, 0.f);
            lsum += acc;
            lsq = fmaf(acc, acc, lsq);
            g_msg[(s + j) * D + lane] = acc;          // coalesced 128B store
        }
        __syncwarp();
    }
    __shared__ float ssum[4][32], ssq[4][32];
    ssum[wid][lane] = lsum; ssq[wid][lane] = lsq;
    __syncthreads();
    if (wid == 0) {
        float ts = ssum[0][lane] + ssum[1][lane] + ssum[2][lane] + ssum[3][lane];
        float tq = ssq[0][lane] + ssq[1][lane] + ssq[2][lane] + ssq[3][lane];
        atomicAdd(&g_sum[lane], ts);
        atomicAdd(&g_sumsq[lane], tq);
    }
}

// ---------------- K6: gather reduce + folded BN finalize -----------------
__global__ void __launch_bounds__(128) k6_reduce(
    float* __restrict__ out, const float* __restrict__ gamma,
    const float* __restrict__ beta)
{
    __shared__ float s_sc[32], s_sh[32];
    if (threadIdx.x < 32) {
        int d = threadIdx.x;
        float inv_e = 1.0f / (float)N_EDGES;
        float mu = g_sum[d] * inv_e;
        float var = fmaxf(g_sumsq[d] * inv_e - mu * mu, 0.f);
        float scale = rsqrtf(var + EPS) * gamma[d];
        s_sc[d] = scale;
        s_sh[d] = beta[d] - mu * scale;
    }
    __syncthreads();

    const int lane = threadIdx.x & 31;
    const int node = (blockIdx.x * blockDim.x + threadIdx.x) >> 5;
    if (node >= N_NODES) return;
    const float sc = s_sc[lane], shf = s_sh[lane];

    int off = g_doff[node], end = g_doff[node + 1];
    int cnt = end - off;
    float acc = 0.f;
    int i = off;
    for (; i + 1 < end; i += 2) {
        int p0 = g_eidx2[i];
        int p1 = g_eidx2[i + 1];
        acc += g_msg[p0 * D + lane];
        acc += g_msg[p1 * D + lane];
    }
    if (i < end) acc += g_msg[g_eidx2[i] * D + lane];

    float v = 0.f;
    if (cnt > 0) v = fmaf(acc * (1.0f / (float)cnt), sc, shf);
    out[node * D + lane] = v;
}

extern "C" void kernel_launch(void* const* d_in, const int* in_sizes, int n_in,
                              void* d_out, int out_size) {
    const float* h      = (const float*)d_in[0];
    const float* weight = (const float*)d_in[1];
    const float* gamma  = (const float*)d_in[2];
    const float* beta   = (const float*)d_in[3];
    const int*   src    = (const int*)d_in[4];
    const int*   dst    = (const int*)d_in[5];
    const int*   etype  = (const int*)d_in[6];
    float* out = (float*)d_out;

    k1_hist<<<NB, 256>>>(etype, dst);
    ks_scan<<<2, 1024>>>();
    k3_scatter<<<NB, 256>>>(etype, src, dst);
    k4_compute<<<1600, 128>>>(h, weight);
    k6_reduce<<<(N_NODES * 32 + 127) / 128, 128>>>(out, gamma, beta);
}